// round 1
// baseline (speedup 1.0000x reference)
#include <cuda_runtime.h>
#include <cuda_bf16.h>
#include <math.h>

// Problem constants
#define B_  2
#define S_  2048
#define D_  1024
#define H_  16
#define HD_ 64
#define M_  (B_ * S_)            // 4096 rows for projections
#define BH_ (B_ * H_)            // 32 batch-heads
#define MAXLEN_ 5000

// ---------------- scratch (device globals; no allocation allowed) ----------
__device__ float g_xpe[M_ * D_];                    // 16 MB
__device__ float g_q[M_ * D_];                      // [B,H,S,hd]
__device__ float g_k[M_ * D_];
__device__ float g_v[M_ * D_];
__device__ float g_ctx[M_ * D_];                    // attention output, [B,S,D]
__device__ float g_scores[(size_t)BH_ * S_ * S_];   // 536 MB

// ---------------- kernel 1: x + mixed positional encoding ------------------
__global__ __launch_bounds__(256) void pe_kernel(
    const float* __restrict__ x, const float* __restrict__ rel,
    const float* __restrict__ alpha_p, float* __restrict__ xpe)
{
    const int bs = blockIdx.x;            // 0..4095 (b*2048 + s)
    const int s  = bs & (S_ - 1);
    const float alpha = alpha_p[0];
    const float beta  = 1.0f - alpha;
    const size_t base  = (size_t)bs * D_;
    const size_t rbase = (size_t)(MAXLEN_ - S_ + s) * D_;
    const float kC = (float)(-9.210340371976184 / 1024.0);  // -ln(10000)/D

    #pragma unroll
    for (int t = 0; t < 2; t++) {
        int p  = threadIdx.x * 2 + t;     // pair index 0..511
        int d0 = p * 2;
        float divv = expf((float)d0 * kC);
        float ang  = (float)s * divv;
        float sn, cs;
        sincosf(ang, &sn, &cs);
        float m0 = alpha * sn + beta * rel[rbase + d0];
        float m1 = alpha * cs + beta * rel[rbase + d0 + 1];
        xpe[base + d0]     = x[base + d0]     + m0;
        xpe[base + d0 + 1] = x[base + d0 + 1] + m1;
    }
}

// ---------------- generic TN GEMM: C = A[M,K] * B[N,K]^T * scale (+bias) ---
// 64x64 tile, BK=16, 256 threads, 4x4 micro-tile per thread.
// mode 0: C[z*strideC + m*N + n]
// mode 1: head layout for Q/K/V: [B,H,S,hd] (z must be 1)
__global__ __launch_bounds__(256) void gemm_tn(
    const float* __restrict__ A, const float* __restrict__ B,
    const float* __restrict__ bias, float* __restrict__ C,
    int M, int N, int K,
    size_t strideA, size_t strideB, size_t strideC,
    float scale, int mode)
{
    __shared__ float As[16][65];
    __shared__ float Bs[16][65];

    const float* Ab = A + (size_t)blockIdx.z * strideA;
    const float* Bb = B + (size_t)blockIdx.z * strideB;

    const int bm = blockIdx.y * 64;
    const int bn = blockIdx.x * 64;
    const int tx = threadIdx.x & 15;
    const int ty = threadIdx.x >> 4;

    const int lr = threadIdx.x >> 2;          // row within tile for loads
    const int lk = (threadIdx.x & 3) * 4;     // k offset for loads

    float acc[4][4] = {};

    for (int k0 = 0; k0 < K; k0 += 16) {
        {
            float4 a = *reinterpret_cast<const float4*>(
                &Ab[(size_t)(bm + lr) * K + k0 + lk]);
            As[lk + 0][lr] = a.x; As[lk + 1][lr] = a.y;
            As[lk + 2][lr] = a.z; As[lk + 3][lr] = a.w;
        }
        {
            float4 b = *reinterpret_cast<const float4*>(
                &Bb[(size_t)(bn + lr) * K + k0 + lk]);
            Bs[lk + 0][lr] = b.x; Bs[lk + 1][lr] = b.y;
            Bs[lk + 2][lr] = b.z; Bs[lk + 3][lr] = b.w;
        }
        __syncthreads();
        #pragma unroll
        for (int k = 0; k < 16; k++) {
            float ar[4], br[4];
            #pragma unroll
            for (int i = 0; i < 4; i++) ar[i] = As[k][ty * 4 + i];
            #pragma unroll
            for (int j = 0; j < 4; j++) br[j] = Bs[k][tx * 4 + j];
            #pragma unroll
            for (int i = 0; i < 4; i++)
                #pragma unroll
                for (int j = 0; j < 4; j++)
                    acc[i][j] = fmaf(ar[i], br[j], acc[i][j]);
        }
        __syncthreads();
    }

    #pragma unroll
    for (int i = 0; i < 4; i++) {
        int m = bm + ty * 4 + i;
        #pragma unroll
        for (int j = 0; j < 4; j++) {
            int n = bn + tx * 4 + j;
            float val = acc[i][j] * scale;
            if (bias) val += bias[n];
            if (mode == 1) {
                int b = m >> 11, s = m & (S_ - 1);
                int h = n >> 6,  hd = n & 63;
                C[((((size_t)b * H_ + h) * S_ + s) << 6) + hd] = val;
            } else {
                C[(size_t)blockIdx.z * strideC + (size_t)m * N + n] = val;
            }
        }
    }
}

// ---------------- softmax over rows of length 2048 --------------------------
__global__ __launch_bounds__(256) void softmax_kernel(float* __restrict__ sc)
{
    __shared__ float red[8];
    const int tid = threadIdx.x;
    float* row = sc + (size_t)blockIdx.x * S_;

    float v[8];
    float mx = -1e30f;
    #pragma unroll
    for (int i = 0; i < 8; i++) {
        v[i] = row[i * 256 + tid];
        mx = fmaxf(mx, v[i]);
    }
    #pragma unroll
    for (int o = 16; o > 0; o >>= 1) mx = fmaxf(mx, __shfl_xor_sync(~0u, mx, o));
    if ((tid & 31) == 0) red[tid >> 5] = mx;
    __syncthreads();
    mx = red[0];
    #pragma unroll
    for (int w = 1; w < 8; w++) mx = fmaxf(mx, red[w]);
    __syncthreads();

    float sum = 0.0f;
    #pragma unroll
    for (int i = 0; i < 8; i++) {
        v[i] = expf(v[i] - mx);
        sum += v[i];
    }
    #pragma unroll
    for (int o = 16; o > 0; o >>= 1) sum += __shfl_xor_sync(~0u, sum, o);
    if ((tid & 31) == 0) red[tid >> 5] = sum;
    __syncthreads();
    sum = 0.0f;
    #pragma unroll
    for (int w = 0; w < 8; w++) sum += red[w];
    float inv = 1.0f / sum;
    #pragma unroll
    for (int i = 0; i < 8; i++) row[i * 256 + tid] = v[i] * inv;
}

// ---------------- PV GEMM: ctx[b,s, h*64+n] = sum_k P[m,k] * V[k,n] --------
// NN form: P [2048,2048] row-major, V [2048,64] row-major per batch-head.
__global__ __launch_bounds__(256) void gemm_pv(
    const float* __restrict__ P, const float* __restrict__ V,
    float* __restrict__ ctx)
{
    __shared__ float As[16][65];
    __shared__ float Bs[16][64];

    const int z = blockIdx.z;                 // batch-head
    const float* Pb = P + (size_t)z * S_ * S_;
    const float* Vb = V + (size_t)z * S_ * HD_;

    const int bm = blockIdx.x * 64;
    const int tx = threadIdx.x & 15;
    const int ty = threadIdx.x >> 4;

    float acc[4][4] = {};

    for (int k0 = 0; k0 < S_; k0 += 16) {
        {
            int r  = threadIdx.x >> 2;
            int kk = (threadIdx.x & 3) * 4;
            float4 a = *reinterpret_cast<const float4*>(
                &Pb[(size_t)(bm + r) * S_ + k0 + kk]);
            As[kk + 0][r] = a.x; As[kk + 1][r] = a.y;
            As[kk + 2][r] = a.z; As[kk + 3][r] = a.w;
        }
        {
            int k  = threadIdx.x >> 4;
            int nn = (threadIdx.x & 15) * 4;
            *reinterpret_cast<float4*>(&Bs[k][nn]) =
                *reinterpret_cast<const float4*>(&Vb[(size_t)(k0 + k) * HD_ + nn]);
        }
        __syncthreads();
        #pragma unroll
        for (int k = 0; k < 16; k++) {
            float ar[4], br[4];
            #pragma unroll
            for (int i = 0; i < 4; i++) ar[i] = As[k][ty * 4 + i];
            #pragma unroll
            for (int j = 0; j < 4; j++) br[j] = Bs[k][tx * 4 + j];
            #pragma unroll
            for (int i = 0; i < 4; i++)
                #pragma unroll
                for (int j = 0; j < 4; j++)
                    acc[i][j] = fmaf(ar[i], br[j], acc[i][j]);
        }
        __syncthreads();
    }

    const int b = z >> 4, h = z & 15;
    #pragma unroll
    for (int i = 0; i < 4; i++) {
        int s = bm + ty * 4 + i;
        #pragma unroll
        for (int j = 0; j < 4; j++) {
            int n = tx * 4 + j;
            ctx[((size_t)(b * S_ + s)) * D_ + h * HD_ + n] = acc[i][j];
        }
    }
}

// ---------------- host: graph-capturable launch sequence --------------------
extern "C" void kernel_launch(void* const* d_in, const int* in_sizes, int n_in,
                              void* d_out, int out_size)
{
    (void)in_sizes; (void)n_in; (void)out_size;

    const float* x     = (const float*)d_in[0];
    const float* rel   = (const float*)d_in[1];
    const float* alpha = (const float*)d_in[2];
    const float* Wq    = (const float*)d_in[3];
    const float* bq    = (const float*)d_in[4];
    const float* Wk    = (const float*)d_in[5];
    const float* bk    = (const float*)d_in[6];
    const float* Wv    = (const float*)d_in[7];
    const float* bv    = (const float*)d_in[8];
    const float* Wo    = (const float*)d_in[9];
    const float* bo    = (const float*)d_in[10];
    float* out = (float*)d_out;

    void* p;
    cudaGetSymbolAddress(&p, g_xpe);    float* xpe    = (float*)p;
    cudaGetSymbolAddress(&p, g_q);      float* q      = (float*)p;
    cudaGetSymbolAddress(&p, g_k);      float* k      = (float*)p;
    cudaGetSymbolAddress(&p, g_v);      float* v      = (float*)p;
    cudaGetSymbolAddress(&p, g_ctx);    float* ctx    = (float*)p;
    cudaGetSymbolAddress(&p, g_scores); float* scores = (float*)p;

    // 1) positional encoding
    pe_kernel<<<M_, 256>>>(x, rel, alpha, xpe);

    // 2) Q/K/V projections -> [B,H,S,hd]
    dim3 gproj(D_ / 64, M_ / 64, 1);
    gemm_tn<<<gproj, 256>>>(xpe, Wq, bq, q, M_, D_, D_, 0, 0, 0, 1.0f, 1);
    gemm_tn<<<gproj, 256>>>(xpe, Wk, bk, k, M_, D_, D_, 0, 0, 0, 1.0f, 1);
    gemm_tn<<<gproj, 256>>>(xpe, Wv, bv, v, M_, D_, D_, 0, 0, 0, 1.0f, 1);

    // 3) scores = Q K^T / sqrt(D)   (batched over 32 batch-heads)
    dim3 gqk(S_ / 64, S_ / 64, BH_);
    gemm_tn<<<gqk, 256>>>(q, k, nullptr, scores, S_, S_, HD_,
                          (size_t)S_ * HD_, (size_t)S_ * HD_,
                          (size_t)S_ * S_, 0.03125f, 0);

    // 4) row softmax
    softmax_kernel<<<BH_ * S_, 256>>>(scores);

    // 5) ctx = P V  -> [B,S,D]
    dim3 gpv(S_ / 64, 1, BH_);
    gemm_pv<<<gpv, 256>>>(scores, v, ctx);

    // 6) output projection
    gemm_tn<<<gproj, 256>>>(ctx, Wo, bo, out, M_, D_, D_, 0, 0, 0, 1.0f, 0);
}

// round 3
// speedup vs baseline: 3.0779x; 3.0779x over previous
#include <cuda_runtime.h>
#include <cuda_bf16.h>
#include <math.h>
#include <cstdint>

#define B_  2
#define S_  2048
#define D_  1024
#define H_  16
#define HD_ 64
#define M_  (B_ * S_)
#define BH_ (B_ * H_)
#define MAXLEN_ 5000

// ---------------- scratch (device globals) ----------------------------------
__device__ float g_xpe[M_ * D_];
__device__ float g_q[M_ * D_];
__device__ float g_k[M_ * D_];
__device__ float g_v[M_ * D_];
__device__ float g_ctx[M_ * D_];
__device__ float g_scores[(size_t)BH_ * S_ * S_];

// ---------------- helpers ----------------------------------------------------
__device__ __forceinline__ uint32_t smem_u32(const void* p) {
    uint32_t a;
    asm("{ .reg .u64 t; cvta.to.shared.u64 t, %1; cvt.u32.u64 %0, t; }"
        : "=r"(a) : "l"(p));
    return a;
}
__device__ __forceinline__ uint32_t f2tf(float f) {
    uint32_t r;
    asm("cvt.rna.tf32.f32 %0, %1;" : "=r"(r) : "f"(f));
    return r;
}
__device__ __forceinline__ void mma8(float* c, const uint32_t* a, const uint32_t* b) {
    asm volatile(
        "mma.sync.aligned.m16n8k8.row.col.f32.tf32.tf32.f32 "
        "{%0,%1,%2,%3}, {%4,%5,%6,%7}, {%8,%9}, {%0,%1,%2,%3};"
        : "+f"(c[0]), "+f"(c[1]), "+f"(c[2]), "+f"(c[3])
        : "r"(a[0]), "r"(a[1]), "r"(a[2]), "r"(a[3]), "r"(b[0]), "r"(b[1]));
}
#define CP16(dst, src) \
    asm volatile("cp.async.cg.shared.global [%0], [%1], 16;" \
        :: "r"(dst), "l"(src) : "memory")
#define CP_COMMIT() asm volatile("cp.async.commit_group;" ::: "memory")

// ---------------- kernel 1: x + mixed positional encoding -------------------
__global__ __launch_bounds__(256) void pe_kernel(
    const float* __restrict__ x, const float* __restrict__ rel,
    const float* __restrict__ alpha_p, float* __restrict__ xpe)
{
    const int bs = blockIdx.x;
    const int s  = bs & (S_ - 1);
    const float alpha = alpha_p[0];
    const float beta  = 1.0f - alpha;
    const size_t base  = (size_t)bs * D_;
    const size_t rbase = (size_t)(MAXLEN_ - S_ + s) * D_;
    const float kC = (float)(-9.210340371976184 / 1024.0);

    #pragma unroll
    for (int t = 0; t < 2; t++) {
        int p  = threadIdx.x * 2 + t;
        int d0 = p * 2;
        float divv = expf((float)d0 * kC);
        float ang  = (float)s * divv;
        float sn, cs;
        sincosf(ang, &sn, &cs);
        float m0 = alpha * sn + beta * rel[rbase + d0];
        float m1 = alpha * cs + beta * rel[rbase + d0 + 1];
        xpe[base + d0]     = x[base + d0]     + m0;
        xpe[base + d0 + 1] = x[base + d0 + 1] + m1;
    }
}

// ---------------- tf32 mma.sync GEMM -----------------------------------------
// TN form: C = A[M,K] * B[N,K]^T * scale (+bias)
// MODE 0: O-proj  [4096,1024]x[1024,1024]
// MODE 1: QKV     same, output scattered to [B,H,S,hd]
// MODE 2: QK^T    per z: [2048,64]x[2048,64] -> [2048,2048]
// MODE 3: PV      per z: P[2048,2048] * V[2048,64] (V transposed on load)
template<int MODE>
__global__ __launch_bounds__(256) void mma_gemm(
    const float* __restrict__ A, const float* __restrict__ Bm,
    const float* __restrict__ bias, float* __restrict__ C, float scale)
{
    constexpr int BM = 128, BK = 32;
    constexpr int BN   = (MODE == 3) ? 64 : 128;
    constexpr int KTOT = (MODE == 2) ? 64 : ((MODE == 3) ? 2048 : 1024);
    constexpr int LDA  = (MODE == 2) ? 64 : ((MODE == 3) ? 2048 : 1024);
    constexpr int LDB  = (MODE == 2) ? 64 : 1024;
    constexpr int NK   = KTOT / BK;
    constexpr int SA   = 36;               // row stride (floats): conflict-free
    constexpr int ASZ  = BM * SA;
    constexpr int BSZ  = BN * SA;
    constexpr int STG  = ASZ + BSZ;
    constexpr int NF   = BN / 16;          // n-fragments per warp (8 or 4)

    extern __shared__ __align__(16) float sm[];
    const int tid  = threadIdx.x;
    const int wid  = tid >> 5, lane = tid & 31;
    const int gid  = lane >> 2, tig = lane & 3;
    const int wm   = wid & 3;              // 4 warps along M
    const int wn   = wid >> 2;             // 2 warps along N

    const int bm = blockIdx.y * BM;
    const int bn = blockIdx.x * BN;
    const int z  = blockIdx.z;

    const float* Ab = A  + ((MODE == 2) ? (size_t)z * S_ * HD_
                          : (MODE == 3) ? (size_t)z * S_ * S_ : (size_t)0);
    const float* Bb = Bm + ((MODE >= 2) ? (size_t)z * S_ * HD_ : (size_t)0);

    float acc[2][NF][4];
    #pragma unroll
    for (int i = 0; i < 2; i++)
        #pragma unroll
        for (int j = 0; j < NF; j++)
            #pragma unroll
            for (int r = 0; r < 4; r++) acc[i][j][r] = 0.0f;

    // stage loader
    auto load_stage = [&](int kc, int buf) {
        float* sA = sm + buf * STG;
        float* sB = sA + ASZ;
        const float* Ap = Ab + (size_t)bm * LDA + kc * BK;
        uint32_t sAu = smem_u32(sA);
        #pragma unroll
        for (int i = 0; i < BM * BK / 1024; i++) {        // 4 iters
            int f = tid + i * 256;
            int m = f >> 3, c = f & 7;
            CP16(sAu + (uint32_t)(m * SA + c * 4) * 4, Ap + (size_t)m * LDA + c * 4);
        }
        if (MODE != 3) {
            const float* Bp = Bb + (size_t)bn * LDB + kc * BK;
            uint32_t sBu = smem_u32(sB);
            #pragma unroll
            for (int i = 0; i < BN * BK / 1024; i++) {
                int f = tid + i * 256;
                int n = f >> 3, c = f & 7;
                CP16(sBu + (uint32_t)(n * SA + c * 4) * 4, Bp + (size_t)n * LDB + c * 4);
            }
        } else {
            // V transpose: sB[n][k] = V[kc*32+k][n]
            #pragma unroll
            for (int i = 0; i < BN * BK / 256; i++) {     // 8 iters
                int idx = tid + i * 256;
                int n = idx & 63, k = idx >> 6;
                sB[n * SA + k] = Bb[(size_t)(kc * BK + k) * HD_ + n];
            }
        }
        CP_COMMIT();
    };

    load_stage(0, 0);

    for (int kc = 0; kc < NK; kc++) {
        const int buf = kc & 1;
        if (kc + 1 < NK) {
            load_stage(kc + 1, buf ^ 1);
            asm volatile("cp.async.wait_group 1;" ::: "memory");
        } else {
            asm volatile("cp.async.wait_group 0;" ::: "memory");
        }
        __syncthreads();

        const float* sA = sm + buf * STG;
        const float* sB = sA + ASZ;

        #pragma unroll
        for (int kk = 0; kk < BK; kk += 8) {
            uint32_t a[2][4];
            #pragma unroll
            for (int mf = 0; mf < 2; mf++) {
                int m0 = wm * 32 + mf * 16 + gid;
                a[mf][0] = f2tf(sA[m0 * SA + kk + tig]);
                a[mf][1] = f2tf(sA[(m0 + 8) * SA + kk + tig]);
                a[mf][2] = f2tf(sA[m0 * SA + kk + tig + 4]);
                a[mf][3] = f2tf(sA[(m0 + 8) * SA + kk + tig + 4]);
            }
            uint32_t b[NF][2];
            #pragma unroll
            for (int nf = 0; nf < NF; nf++) {
                int n0 = wn * (BN / 2) + nf * 8 + gid;
                b[nf][0] = f2tf(sB[n0 * SA + kk + tig]);
                b[nf][1] = f2tf(sB[n0 * SA + kk + tig + 4]);
            }
            #pragma unroll
            for (int mf = 0; mf < 2; mf++)
                #pragma unroll
                for (int nf = 0; nf < NF; nf++)
                    mma8(acc[mf][nf], a[mf], b[nf]);
        }
        __syncthreads();
    }

    // ---- epilogue: direct float2 stores -------------------------------------
    #pragma unroll
    for (int mf = 0; mf < 2; mf++) {
        #pragma unroll
        for (int r = 0; r < 2; r++) {
            int m = bm + wm * 32 + mf * 16 + gid + r * 8;
            #pragma unroll
            for (int nf = 0; nf < NF; nf++) {
                int n = bn + wn * (BN / 2) + nf * 8 + 2 * tig;
                float v0 = acc[mf][nf][r * 2 + 0] * scale;
                float v1 = acc[mf][nf][r * 2 + 1] * scale;
                if (MODE == 0) {
                    v0 += bias[n]; v1 += bias[n + 1];
                    *reinterpret_cast<float2*>(&C[(size_t)m * D_ + n]) =
                        make_float2(v0, v1);
                } else if (MODE == 1) {
                    v0 += bias[n]; v1 += bias[n + 1];
                    int b = m >> 11, s = m & (S_ - 1), h = n >> 6, hd = n & 63;
                    *reinterpret_cast<float2*>(
                        &C[((((size_t)b * H_ + h) * S_ + s) << 6) + hd]) =
                        make_float2(v0, v1);
                } else if (MODE == 2) {
                    *reinterpret_cast<float2*>(
                        &C[(size_t)z * S_ * S_ + (size_t)m * S_ + n]) =
                        make_float2(v0, v1);
                } else {
                    int b = z >> 4, h = z & 15;
                    *reinterpret_cast<float2*>(
                        &C[((size_t)(b * S_ + m)) * D_ + h * HD_ + n]) =
                        make_float2(v0, v1);
                }
            }
        }
    }
}

// ---------------- softmax over rows of length 2048 ---------------------------
__global__ __launch_bounds__(256) void softmax_kernel(float* __restrict__ sc)
{
    __shared__ float red[8];
    const int tid = threadIdx.x;
    float* row = sc + (size_t)blockIdx.x * S_;

    float v[8];
    float mx = -1e30f;
    #pragma unroll
    for (int i = 0; i < 8; i++) {
        v[i] = row[i * 256 + tid];
        mx = fmaxf(mx, v[i]);
    }
    #pragma unroll
    for (int o = 16; o > 0; o >>= 1) mx = fmaxf(mx, __shfl_xor_sync(~0u, mx, o));
    if ((tid & 31) == 0) red[tid >> 5] = mx;
    __syncthreads();
    mx = red[0];
    #pragma unroll
    for (int w = 1; w < 8; w++) mx = fmaxf(mx, red[w]);
    __syncthreads();

    float sum = 0.0f;
    #pragma unroll
    for (int i = 0; i < 8; i++) {
        v[i] = expf(v[i] - mx);
        sum += v[i];
    }
    #pragma unroll
    for (int o = 16; o > 0; o >>= 1) sum += __shfl_xor_sync(~0u, sum, o);
    if ((tid & 31) == 0) red[tid >> 5] = sum;
    __syncthreads();
    sum = 0.0f;
    #pragma unroll
    for (int w = 0; w < 8; w++) sum += red[w];
    float inv = 1.0f / sum;
    #pragma unroll
    for (int i = 0; i < 8; i++) row[i * 256 + tid] = v[i] * inv;
}

// ---------------- host launch sequence ---------------------------------------
extern "C" void kernel_launch(void* const* d_in, const int* in_sizes, int n_in,
                              void* d_out, int out_size)
{
    (void)in_sizes; (void)n_in; (void)out_size;

    const float* x     = (const float*)d_in[0];
    const float* rel   = (const float*)d_in[1];
    const float* alpha = (const float*)d_in[2];
    const float* Wq    = (const float*)d_in[3];
    const float* bq    = (const float*)d_in[4];
    const float* Wk    = (const float*)d_in[5];
    const float* bk    = (const float*)d_in[6];
    const float* Wv    = (const float*)d_in[7];
    const float* bv    = (const float*)d_in[8];
    const float* Wo    = (const float*)d_in[9];
    const float* bo    = (const float*)d_in[10];
    float* out = (float*)d_out;

    void* p;
    cudaGetSymbolAddress(&p, g_xpe);    float* xpe    = (float*)p;
    cudaGetSymbolAddress(&p, g_q);      float* q      = (float*)p;
    cudaGetSymbolAddress(&p, g_k);      float* k      = (float*)p;
    cudaGetSymbolAddress(&p, g_v);      float* v      = (float*)p;
    cudaGetSymbolAddress(&p, g_ctx);    float* ctx    = (float*)p;
    cudaGetSymbolAddress(&p, g_scores); float* scores = (float*)p;

    // dynamic smem: 2 stages of (A + B) tiles
    const int SMEM_BIG = 2 * (128 * 36 + 128 * 36) * 4;  // 73728
    const int SMEM_PV  = 2 * (128 * 36 + 64 * 36) * 4;   // 55296
    cudaFuncSetAttribute(mma_gemm<0>, cudaFuncAttributeMaxDynamicSharedMemorySize, SMEM_BIG);
    cudaFuncSetAttribute(mma_gemm<1>, cudaFuncAttributeMaxDynamicSharedMemorySize, SMEM_BIG);
    cudaFuncSetAttribute(mma_gemm<2>, cudaFuncAttributeMaxDynamicSharedMemorySize, SMEM_BIG);
    cudaFuncSetAttribute(mma_gemm<3>, cudaFuncAttributeMaxDynamicSharedMemorySize, SMEM_PV);

    // 1) positional encoding
    pe_kernel<<<M_, 256>>>(x, rel, alpha, xpe);

    // 2) Q/K/V projections -> [B,H,S,hd]
    dim3 gproj(D_ / 128, M_ / 128, 1);
    mma_gemm<1><<<gproj, 256, SMEM_BIG>>>(xpe, Wq, bq, q, 1.0f);
    mma_gemm<1><<<gproj, 256, SMEM_BIG>>>(xpe, Wk, bk, k, 1.0f);
    mma_gemm<1><<<gproj, 256, SMEM_BIG>>>(xpe, Wv, bv, v, 1.0f);

    // 3) scores = Q K^T / 32
    dim3 gqk(S_ / 128, S_ / 128, BH_);
    mma_gemm<2><<<gqk, 256, SMEM_BIG>>>(q, k, nullptr, scores, 0.03125f);

    // 4) softmax
    softmax_kernel<<<BH_ * S_, 256>>>(scores);

    // 5) ctx = P V
    dim3 gpv(1, S_ / 128, BH_);
    mma_gemm<3><<<gpv, 256, SMEM_PV>>>(scores, v, nullptr, ctx, 1.0f);

    // 6) output projection
    mma_gemm<0><<<gproj, 256, SMEM_BIG>>>(ctx, Wo, bo, out, 1.0f);
}

// round 4
// speedup vs baseline: 3.0927x; 1.0048x over previous
#include <cuda_runtime.h>
#include <cuda_bf16.h>
#include <math.h>
#include <cstdint>

#define B_  2
#define S_  2048
#define D_  1024
#define H_  16
#define HD_ 64
#define M_  (B_ * S_)
#define BH_ (B_ * H_)
#define MAXLEN_ 5000

// ---------------- scratch (device globals) ----------------------------------
__device__ float g_xpe[M_ * D_];
__device__ float g_q[M_ * D_];
__device__ float g_k[M_ * D_];
__device__ float g_v[M_ * D_];
__device__ float g_ctx[M_ * D_];
__device__ float g_scores[(size_t)BH_ * S_ * S_];
__device__ float g_wq[D_ * D_];
__device__ float g_wk[D_ * D_];
__device__ float g_wv[D_ * D_];
__device__ float g_wo[D_ * D_];

// ---------------- helpers ----------------------------------------------------
__device__ __forceinline__ uint32_t smem_u32(const void* p) {
    uint32_t a;
    asm("{ .reg .u64 t; cvta.to.shared.u64 t, %1; cvt.u32.u64 %0, t; }"
        : "=r"(a) : "l"(p));
    return a;
}
__device__ __forceinline__ float f2tf_f(float f) {
    uint32_t r;
    asm("cvt.rna.tf32.f32 %0, %1;" : "=r"(r) : "f"(f));
    return __uint_as_float(r);
}
// within-8 k permutation: k -> 2*(k&3) | (k>>2)
__device__ __forceinline__ int pcol(int k) {
    return (k & ~7) | (((k & 3) << 1) | ((k >> 2) & 1));
}
__device__ __forceinline__ void mma8(float* c, const uint32_t* a, const uint32_t* b) {
    asm volatile(
        "mma.sync.aligned.m16n8k8.row.col.f32.tf32.tf32.f32 "
        "{%0,%1,%2,%3}, {%4,%5,%6,%7}, {%8,%9}, {%0,%1,%2,%3};"
        : "+f"(c[0]), "+f"(c[1]), "+f"(c[2]), "+f"(c[3])
        : "r"(a[0]), "r"(a[1]), "r"(a[2]), "r"(a[3]), "r"(b[0]), "r"(b[1]));
}
#define CP16(dst, src) \
    asm volatile("cp.async.cg.shared.global [%0], [%1], 16;" \
        :: "r"(dst), "l"(src) : "memory")
#define CP_COMMIT() asm volatile("cp.async.commit_group;" ::: "memory")

// ---------------- weight prep: tf32-round + k-permute ------------------------
__global__ __launch_bounds__(256) void wprep_kernel(
    const float* __restrict__ src, float* __restrict__ dst)
{
    int base = (blockIdx.x * 256 + threadIdx.x) * 4;
    #pragma unroll
    for (int i = 0; i < 4; i++) {
        int idx = base + i;
        int n = idx >> 10, k = idx & 1023;
        dst[(n << 10) | pcol(k)] = f2tf_f(src[idx]);
    }
}

// ---------------- kernel 1: x + PE, tf32-rounded, k-permuted -----------------
__global__ __launch_bounds__(256) void pe_kernel(
    const float* __restrict__ x, const float* __restrict__ rel,
    const float* __restrict__ alpha_p, float* __restrict__ xpe)
{
    const int bs = blockIdx.x;
    const int s  = bs & (S_ - 1);
    const float alpha = alpha_p[0];
    const float beta  = 1.0f - alpha;
    const size_t base  = (size_t)bs * D_;
    const size_t rbase = (size_t)(MAXLEN_ - S_ + s) * D_;
    const float kC = (float)(-9.210340371976184 / 1024.0);

    #pragma unroll
    for (int t = 0; t < 2; t++) {
        int p  = threadIdx.x * 2 + t;
        int d0 = p * 2;
        float divv = expf((float)d0 * kC);
        float ang  = (float)s * divv;
        float sn, cs;
        sincosf(ang, &sn, &cs);
        float m0 = alpha * sn + beta * rel[rbase + d0];
        float m1 = alpha * cs + beta * rel[rbase + d0 + 1];
        xpe[base + pcol(d0)]     = f2tf_f(x[base + d0]     + m0);
        xpe[base + pcol(d0 + 1)] = f2tf_f(x[base + d0 + 1] + m1);
    }
}

// ---------------- tf32 mma.sync GEMM (operands pre-rounded + k-permuted) -----
// MODE 0: O-proj  C = ctx * Wo^T + bo          (plain output)
// MODE 1: Q/K     output scattered [B,H,S,hd], hd k-permuted + rounded
// MODE 4: V       output scattered [B,H,S,hd], natural hd, rounded
// MODE 2: QK^T    per z: scores (natural, fp32)
// MODE 3: PV      per z: ctx (rounded, column-permuted for O-proj)
template<int MODE>
__global__ __launch_bounds__(256) void mma_gemm(
    const float* __restrict__ A, const float* __restrict__ Bm,
    const float* __restrict__ bias, float* __restrict__ C, float scale)
{
    constexpr int BM = 128, BK = 32;
    constexpr int BN   = (MODE == 3) ? 64 : 128;
    constexpr int KTOT = (MODE == 2) ? 64 : ((MODE == 3) ? 2048 : 1024);
    constexpr int LDA  = (MODE == 2) ? 64 : ((MODE == 3) ? 2048 : 1024);
    constexpr int LDB  = (MODE == 2) ? 64 : 1024;
    constexpr int NK   = KTOT / BK;
    constexpr int SA   = 40;               // stride: conflict-free for v2 frags
    constexpr int ASZ  = BM * SA;
    constexpr int BSZ  = BN * SA;
    constexpr int STG  = ASZ + BSZ;
    constexpr int NF   = BN / 16;

    extern __shared__ __align__(16) float sm[];
    const int tid  = threadIdx.x;
    const int wid  = tid >> 5, lane = tid & 31;
    const int gid  = lane >> 2, tig = lane & 3;
    const int wm   = wid & 3;
    const int wn   = wid >> 2;

    const int bm = blockIdx.y * BM;
    const int bn = blockIdx.x * BN;
    const int z  = blockIdx.z;

    const float* Ab = A  + ((MODE == 2) ? (size_t)z * S_ * HD_
                          : (MODE == 3) ? (size_t)z * S_ * S_ : (size_t)0);
    const float* Bb = Bm + ((MODE == 2 || MODE == 3) ? (size_t)z * S_ * HD_ : (size_t)0);

    float acc[2][NF][4];
    #pragma unroll
    for (int i = 0; i < 2; i++)
        #pragma unroll
        for (int j = 0; j < NF; j++)
            #pragma unroll
            for (int r = 0; r < 4; r++) acc[i][j][r] = 0.0f;

    auto load_stage = [&](int kc, int buf) {
        float* sA = sm + buf * STG;
        float* sB = sA + ASZ;
        const float* Ap = Ab + (size_t)bm * LDA + kc * BK;
        uint32_t sAu = smem_u32(sA);
        #pragma unroll
        for (int i = 0; i < BM * BK / 1024; i++) {
            int f = tid + i * 256;
            int m = f >> 3, c = f & 7;
            CP16(sAu + (uint32_t)(m * SA + c * 4) * 4, Ap + (size_t)m * LDA + c * 4);
        }
        if (MODE != 3) {
            const float* Bp = Bb + (size_t)bn * LDB + kc * BK;
            uint32_t sBu = smem_u32(sB);
            #pragma unroll
            for (int i = 0; i < BN * BK / 1024; i++) {
                int f = tid + i * 256;
                int n = f >> 3, c = f & 7;
                CP16(sBu + (uint32_t)(n * SA + c * 4) * 4, Bp + (size_t)n * LDB + c * 4);
            }
        } else {
            // V transpose: sB[n][perm(k)] = V[kc*32+k][n] (v pre-rounded)
            #pragma unroll
            for (int i = 0; i < BN * BK / 256; i++) {
                int idx = tid + i * 256;
                int n = idx & 63, k = idx >> 6;
                sB[n * SA + pcol(k)] = Bb[(size_t)(kc * BK + k) * HD_ + n];
            }
        }
        CP_COMMIT();
    };

    load_stage(0, 0);

    for (int kc = 0; kc < NK; kc++) {
        const int buf = kc & 1;
        if (kc + 1 < NK) {
            load_stage(kc + 1, buf ^ 1);
            asm volatile("cp.async.wait_group 1;" ::: "memory");
        } else {
            asm volatile("cp.async.wait_group 0;" ::: "memory");
        }
        __syncthreads();

        const float* sA = sm + buf * STG;
        const float* sB = sA + ASZ;

        #pragma unroll
        for (int kk = 0; kk < BK; kk += 8) {
            // permuted layout: [kk+2*tig, kk+2*tig+1] = original k = tig, tig+4
            uint32_t a[2][4];
            #pragma unroll
            for (int mf = 0; mf < 2; mf++) {
                const float* pa = sA + (wm * 32 + mf * 16 + gid) * SA + kk + 2 * tig;
                float2 w0 = *reinterpret_cast<const float2*>(pa);
                float2 w1 = *reinterpret_cast<const float2*>(pa + 8 * SA);
                a[mf][0] = __float_as_uint(w0.x);
                a[mf][1] = __float_as_uint(w1.x);
                a[mf][2] = __float_as_uint(w0.y);
                a[mf][3] = __float_as_uint(w1.y);
            }
            uint32_t b[NF][2];
            #pragma unroll
            for (int nf = 0; nf < NF; nf++) {
                float2 w = *reinterpret_cast<const float2*>(
                    sB + (wn * (BN / 2) + nf * 8 + gid) * SA + kk + 2 * tig);
                b[nf][0] = __float_as_uint(w.x);
                b[nf][1] = __float_as_uint(w.y);
            }
            #pragma unroll
            for (int mf = 0; mf < 2; mf++)
                #pragma unroll
                for (int nf = 0; nf < NF; nf++)
                    mma8(acc[mf][nf], a[mf], b[nf]);
        }
        __syncthreads();
    }

    // ---- epilogue -----------------------------------------------------------
    #pragma unroll
    for (int mf = 0; mf < 2; mf++) {
        #pragma unroll
        for (int r = 0; r < 2; r++) {
            int m = bm + wm * 32 + mf * 16 + gid + r * 8;
            #pragma unroll
            for (int nf = 0; nf < NF; nf++) {
                int n = bn + wn * (BN / 2) + nf * 8 + 2 * tig;
                float v0 = acc[mf][nf][r * 2 + 0] * scale;
                float v1 = acc[mf][nf][r * 2 + 1] * scale;
                if (MODE == 0) {
                    v0 += bias[n]; v1 += bias[n + 1];
                    *reinterpret_cast<float2*>(&C[(size_t)m * D_ + n]) =
                        make_float2(v0, v1);
                } else if (MODE == 1) {
                    // Q/K: bias, round, permute hd
                    v0 = f2tf_f(v0 + bias[n]);
                    v1 = f2tf_f(v1 + bias[n + 1]);
                    int b = m >> 11, s = m & (S_ - 1);
                    size_t rowb = (((size_t)b * H_ + (n >> 6)) * S_ + s) << 6;
                    C[rowb + pcol(n & 63)]       = v0;
                    C[rowb + pcol((n + 1) & 63)] = v1;
                } else if (MODE == 4) {
                    // V: bias, round, natural hd
                    v0 = f2tf_f(v0 + bias[n]);
                    v1 = f2tf_f(v1 + bias[n + 1]);
                    int b = m >> 11, s = m & (S_ - 1), h = n >> 6, hd = n & 63;
                    *reinterpret_cast<float2*>(
                        &C[((((size_t)b * H_ + h) * S_ + s) << 6) + hd]) =
                        make_float2(v0, v1);
                } else if (MODE == 2) {
                    // scores: natural, full fp32
                    *reinterpret_cast<float2*>(
                        &C[(size_t)z * S_ * S_ + (size_t)m * S_ + n]) =
                        make_float2(v0, v1);
                } else {
                    // ctx: round + permute column (feeds O-proj as K dim)
                    int b = z >> 4, h = z & 15;
                    size_t rowb = ((size_t)(b * S_ + m)) * D_ + h * HD_;
                    C[rowb + pcol(n)]     = f2tf_f(v0);
                    C[rowb + pcol(n + 1)] = f2tf_f(v1);
                }
            }
        }
    }
}

// ---------------- softmax; output tf32-rounded + column-permuted -------------
__global__ __launch_bounds__(256) void softmax_kernel(float* __restrict__ sc)
{
    __shared__ float red[8];
    const int tid = threadIdx.x;
    float* row = sc + (size_t)blockIdx.x * S_;
    const int pofs = (tid & ~7) | (((tid & 3) << 1) | ((tid >> 2) & 1));

    float v[8];
    float mx = -1e30f;
    #pragma unroll
    for (int i = 0; i < 8; i++) {
        v[i] = row[i * 256 + tid];
        mx = fmaxf(mx, v[i]);
    }
    #pragma unroll
    for (int o = 16; o > 0; o >>= 1) mx = fmaxf(mx, __shfl_xor_sync(~0u, mx, o));
    if ((tid & 31) == 0) red[tid >> 5] = mx;
    __syncthreads();
    mx = red[0];
    #pragma unroll
    for (int w = 1; w < 8; w++) mx = fmaxf(mx, red[w]);
    __syncthreads();

    float sum = 0.0f;
    #pragma unroll
    for (int i = 0; i < 8; i++) {
        v[i] = expf(v[i] - mx);
        sum += v[i];
    }
    #pragma unroll
    for (int o = 16; o > 0; o >>= 1) sum += __shfl_xor_sync(~0u, sum, o);
    if ((tid & 31) == 0) red[tid >> 5] = sum;
    __syncthreads();
    sum = 0.0f;
    #pragma unroll
    for (int w = 0; w < 8; w++) sum += red[w];
    float inv = 1.0f / sum;
    // all loads completed before this point (barriers above) -> in-place permute safe
    #pragma unroll
    for (int i = 0; i < 8; i++) row[i * 256 + pofs] = f2tf_f(v[i] * inv);
}

// ---------------- host launch sequence ---------------------------------------
extern "C" void kernel_launch(void* const* d_in, const int* in_sizes, int n_in,
                              void* d_out, int out_size)
{
    (void)in_sizes; (void)n_in; (void)out_size;

    const float* x     = (const float*)d_in[0];
    const float* rel   = (const float*)d_in[1];
    const float* alpha = (const float*)d_in[2];
    const float* Wq    = (const float*)d_in[3];
    const float* bq    = (const float*)d_in[4];
    const float* Wk    = (const float*)d_in[5];
    const float* bk    = (const float*)d_in[6];
    const float* Wv    = (const float*)d_in[7];
    const float* bv    = (const float*)d_in[8];
    const float* Wo    = (const float*)d_in[9];
    const float* bo    = (const float*)d_in[10];
    float* out = (float*)d_out;

    void* p;
    cudaGetSymbolAddress(&p, g_xpe);    float* xpe    = (float*)p;
    cudaGetSymbolAddress(&p, g_q);      float* q      = (float*)p;
    cudaGetSymbolAddress(&p, g_k);      float* k      = (float*)p;
    cudaGetSymbolAddress(&p, g_v);      float* v      = (float*)p;
    cudaGetSymbolAddress(&p, g_ctx);    float* ctx    = (float*)p;
    cudaGetSymbolAddress(&p, g_scores); float* scores = (float*)p;
    cudaGetSymbolAddress(&p, g_wq);     float* wq     = (float*)p;
    cudaGetSymbolAddress(&p, g_wk);     float* wk     = (float*)p;
    cudaGetSymbolAddress(&p, g_wv);     float* wv     = (float*)p;
    cudaGetSymbolAddress(&p, g_wo);     float* wo     = (float*)p;

    const int SMEM_BIG = 2 * (128 * 40 + 128 * 40) * 4;  // 81920
    const int SMEM_PV  = 2 * (128 * 40 + 64 * 40) * 4;   // 61440
    cudaFuncSetAttribute(mma_gemm<0>, cudaFuncAttributeMaxDynamicSharedMemorySize, SMEM_BIG);
    cudaFuncSetAttribute(mma_gemm<1>, cudaFuncAttributeMaxDynamicSharedMemorySize, SMEM_BIG);
    cudaFuncSetAttribute(mma_gemm<4>, cudaFuncAttributeMaxDynamicSharedMemorySize, SMEM_BIG);
    cudaFuncSetAttribute(mma_gemm<2>, cudaFuncAttributeMaxDynamicSharedMemorySize, SMEM_BIG);
    cudaFuncSetAttribute(mma_gemm<3>, cudaFuncAttributeMaxDynamicSharedMemorySize, SMEM_PV);

    // 0) weight prep (round + permute K dim)
    wprep_kernel<<<1024, 256>>>(Wq, wq);
    wprep_kernel<<<1024, 256>>>(Wk, wk);
    wprep_kernel<<<1024, 256>>>(Wv, wv);
    wprep_kernel<<<1024, 256>>>(Wo, wo);

    // 1) positional encoding (round + permute)
    pe_kernel<<<M_, 256>>>(x, rel, alpha, xpe);

    // 2) Q/K/V projections
    dim3 gproj(D_ / 128, M_ / 128, 1);
    mma_gemm<1><<<gproj, 256, SMEM_BIG>>>(xpe, wq, bq, q, 1.0f);
    mma_gemm<1><<<gproj, 256, SMEM_BIG>>>(xpe, wk, bk, k, 1.0f);
    mma_gemm<4><<<gproj, 256, SMEM_BIG>>>(xpe, wv, bv, v, 1.0f);

    // 3) scores = Q K^T / 32
    dim3 gqk(S_ / 128, S_ / 128, BH_);
    mma_gemm<2><<<gqk, 256, SMEM_BIG>>>(q, k, nullptr, scores, 0.03125f);

    // 4) softmax (+ round/permute for PV)
    softmax_kernel<<<BH_ * S_, 256>>>(scores);

    // 5) ctx = P V
    dim3 gpv(1, S_ / 128, BH_);
    mma_gemm<3><<<gpv, 256, SMEM_PV>>>(scores, v, nullptr, ctx, 1.0f);

    // 6) output projection
    mma_gemm<0><<<gproj, 256, SMEM_BIG>>>(ctx, wo, bo, out, 1.0f);
}